// round 6
// baseline (speedup 1.0000x reference)
#include <cuda_runtime.h>

#define B_   32
#define N_   512
#define M_   512
#define D_   64
#define KD   (N_ + M_ - 1)          // 1023 anti-diagonals of the D matrix
#define BIGF 1e10f

// Diag-major distances: g_Dd[b][k][i] = D[i][k-i]  (only valid (k,i) slots written)
__device__ float g_Dd[(size_t)B_ * KD * N_];   // ~67 MB static scratch

// ---------------------------------------------------------------------------
// Kernel 1: distance tiles, written DIAG-MAJOR.
//   D[i][j] = |x_i|^2 + |y_j|^2 - 2 x_i.y_j
// 64x64 tile, 256 threads, 4x4 micro-tile. Norms computed in-block from the
// loaded smem tiles (no separate norm kernel). Tile is transposed through
// smem (stride 66 -> conflict-free diagonal reads) and drained as contiguous
// per-diagonal runs into g_Dd (coalesced).
// ---------------------------------------------------------------------------
#define TS  64
#define SP  68     // smem row stride for Xs/Ys (transposed [k][row])
#define TSP 66     // smem row stride for the output tile (66 mod 32 == 2; diag reads stride 65 -> conflict-free)

__global__ __launch_bounds__(256) void dist_kernel(const float* __restrict__ x,
                                                   const float* __restrict__ y) {
    __shared__ float Xs[D_ * SP];
    __shared__ float Ys[D_ * SP];
    __shared__ float xn[TS], yn[TS];

    const int b  = blockIdx.z;
    const int i0 = blockIdx.y * TS;
    const int j0 = blockIdx.x * TS;
    const float* xb = x + ((size_t)b * N_ + i0) * D_;
    const float* yb = y + ((size_t)b * M_ + j0) * D_;
    const int tid = threadIdx.x;

    // Load 64 rows x 64 dims of each matrix, transposed into smem.
#pragma unroll
    for (int it = 0; it < 4; ++it) {
        int f   = tid + it * 256;
        int row = f & 63;
        int c4  = f >> 6;            // 0..15
        float4 vx = *(const float4*)(xb + row * D_ + c4 * 4);
        float4 vy = *(const float4*)(yb + row * D_ + c4 * 4);
        Xs[(c4 * 4 + 0) * SP + row] = vx.x;
        Xs[(c4 * 4 + 1) * SP + row] = vx.y;
        Xs[(c4 * 4 + 2) * SP + row] = vx.z;
        Xs[(c4 * 4 + 3) * SP + row] = vx.w;
        Ys[(c4 * 4 + 0) * SP + row] = vy.x;
        Ys[(c4 * 4 + 1) * SP + row] = vy.y;
        Ys[(c4 * 4 + 2) * SP + row] = vy.z;
        Ys[(c4 * 4 + 3) * SP + row] = vy.w;
    }
    __syncthreads();

    // Row norms from the smem tiles (threads 0-63: x, 64-127: y).
    if (tid < 64) {
        float s = 0.f;
#pragma unroll
        for (int k = 0; k < D_; ++k) { float v = Xs[k * SP + tid]; s = fmaf(v, v, s); }
        xn[tid] = s;
    } else if (tid < 128) {
        int r = tid - 64;
        float s = 0.f;
#pragma unroll
        for (int k = 0; k < D_; ++k) { float v = Ys[k * SP + r]; s = fmaf(v, v, s); }
        yn[r] = s;
    }
    __syncthreads();

    const int tx = tid & 15, ty = tid >> 4;
    const int ia = ty * 4, ja = tx * 4;

    float acc[4][4] = {};
#pragma unroll
    for (int k = 0; k < D_; ++k) {
        float4 a  = *(const float4*)&Xs[k * SP + ia];
        float4 bb = *(const float4*)&Ys[k * SP + ja];
        float av[4] = {a.x, a.y, a.z, a.w};
        float bv[4] = {bb.x, bb.y, bb.z, bb.w};
#pragma unroll
        for (int r = 0; r < 4; ++r)
#pragma unroll
            for (int c = 0; c < 4; ++c)
                acc[r][c] = fmaf(av[r], bv[c], acc[r][c]);
    }

    float x2v[4], y2v[4];
#pragma unroll
    for (int r = 0; r < 4; ++r) x2v[r] = xn[ia + r];
#pragma unroll
    for (int c = 0; c < 4; ++c) y2v[c] = yn[ja + c];

    __syncthreads();                 // all Xs/Ys reads done -> safe to alias
    float* Ts = Xs;                  // reuse Xs memory: needs 64*66=4224 <= 64*68

#pragma unroll
    for (int r = 0; r < 4; ++r)
#pragma unroll
        for (int c = 0; c < 4; ++c)
            Ts[(ia + r) * TSP + (ja + c)] =
                fmaf(-2.f, acc[r][c], x2v[r] + y2v[c]);
    __syncthreads();

    // Drain the tile diagonal-wise into g_Dd: flat index f over 4096 elements,
    // ordered (k_local asc, i asc). Triangle-decode via sqrt with guards.
    float* Dd = g_Dd + (size_t)b * KD * N_;
    const int kbase = i0 + j0;
#pragma unroll
    for (int it = 0; it < 16; ++it) {
        int f  = it * 256 + tid;                  // 0..4095
        int fr = (f < 2080) ? f : 4095 - f;       // mirror the upper triangle
        int kl = (int)(0.5f * (sqrtf((float)(8 * fr + 1)) - 1.0f));
        if ((kl + 1) * (kl + 2) / 2 <= fr) kl++;  // rounding guards
        if (kl * (kl + 1) / 2 > fr)       kl--;
        int tt = fr - kl * (kl + 1) / 2;
        int i, kg;
        if (f < 2080) { kg = kl;       i = tt;      }
        else          { kg = 126 - kl; i = 63 - tt; }
        int j = kg - i;
        Dd[(size_t)(kbase + kg) * N_ + (i0 + i)] = Ts[i * TSP + j];
    }
}

// ---------------------------------------------------------------------------
// Kernel 2: soft-DTW wavefront DP.
// One block per batch, 128 threads, thread t owns rows 4t+1..4t+4.
// Intra-strip deps are register-carried (v1 = diag k-1, v2 = diag k-2);
// only each strip's bottom row crosses threads, via 3 rotating smem buffers.
// Distances are one coalesced float4 per thread per step, prefetched 3 deep.
// Softmin uses the exact 2-exp form: s = 1 + e^{m-hi} + e^{m-a}.
// ---------------------------------------------------------------------------
__global__ __launch_bounds__(128) void dtw_kernel(float* __restrict__ out) {
    __shared__ float buf[3][132];    // boundary rows; index s: s=0 -> virtual row 0
    const int b = blockIdx.x;
    const int t = threadIdx.x;       // rows i = 4t+1 .. 4t+4

    const float4* Dd = (const float4*)(g_Dd + (size_t)b * KD * N_) + t; // row stride = 128 float4

    buf[0][t] = BIGF; buf[1][t] = BIGF; buf[2][t] = BIGF;
    if (t == 0) { buf[0][128] = BIGF; buf[1][128] = BIGF; buf[2][128] = BIGF; }

    float v1[4] = {BIGF, BIGF, BIGF, BIGF};   // diag k-1 (init: diag 1 = all BIG)
    float v2[4] = {BIGF, BIGF, BIGF, BIGF};   // diag k-2 (init: diag 0, rows>=1 = BIG)

    float4 d0 = Dd[0 * 128];   // distances for k=2 (D-diag 0)
    float4 d1 = Dd[1 * 128];   // k=3
    float4 d2 = Dd[2 * 128];   // k=4

    float* bk  = buf[2];       // write diag k   (k=2 -> 2%3)
    float* bm1 = buf[1];       // diag k-1
    float* bm2 = buf[0];       // diag k-2

    __syncthreads();

    const int i_top = 4 * t + 1;
#pragma unroll 3
    for (int k = 2; k <= N_ + M_; ++k) {
        // prefetch D-diag (k+1), consumed at iteration k+3
        float4 dn = d2;
        if (k <= KD - 2) dn = Dd[(k + 1) * 128];

        float sb1 = bm1[t];    // row 4t @ diag k-1 (prev thread's bottom row)
        float sb2 = bm2[t];    // row 4t @ diag k-2
        float top_r1 = (t == 0) ? BIGF : sb1;                        // R[0][j>=1] = BIG
        float top_r0 = (t == 0) ? ((k == 2) ? 0.f : BIGF) : sb2;     // R[0][0] = 0

        float dd[4] = {d0.x, d0.y, d0.z, d0.w};
        float nv[4];
#pragma unroll
        for (int r = 0; r < 4; ++r) {
            float r1 = (r == 0) ? top_r1 : v1[r - 1];   // R[i-1][j]
            float r0 = (r == 0) ? top_r0 : v2[r - 1];   // R[i-1][j-1]
            float r2 = v1[r];                            // R[i][j-1]
            float lo = fminf(r1, r2);
            float hi = fmaxf(r1, r2);
            float m  = fminf(lo, r0);
            float a  = fmaxf(lo, r0);
            // exact: sum of the three exps, with the min's term == 1
            float s  = 1.0f + __expf(m - hi) + __expf(m - a);
            float val = dd[r] + m - __logf(s);
            int i = i_top + r;
            int j = k - i;
            nv[r] = (j >= 1 && j <= M_) ? val : BIGF;
        }
        bk[t + 1] = nv[3];     // publish bottom row (row 4t+4) @ diag k
#pragma unroll
        for (int r = 0; r < 4; ++r) { v2[r] = v1[r]; v1[r] = nv[r]; }
        d0 = d1; d1 = d2; d2 = dn;
        float* tmp = bm2; bm2 = bm1; bm1 = bk; bk = tmp;
        __syncthreads();
    }

    if (t == 127) out[b] = v1[3];   // R[512][512]
}

// ---------------------------------------------------------------------------
extern "C" void kernel_launch(void* const* d_in, const int* in_sizes, int n_in,
                              void* d_out, int out_size) {
    const float* x = (const float*)d_in[0];
    const float* y = (const float*)d_in[1];
    float* out = (float*)d_out;

    dim3 dgrid(M_ / TS, N_ / TS, B_);
    dist_kernel<<<dgrid, 256>>>(x, y);
    dtw_kernel<<<B_, 128>>>(out);
}

// round 7
// speedup vs baseline: 1.3231x; 1.3231x over previous
#include <cuda_runtime.h>

#define B_   32
#define N_   512
#define M_   512
#define D_   64
#define KD   (N_ + M_ - 1)          // 1023 anti-diagonals of the D matrix
#define BIGF 1e10f
#define INV_LN2 1.4426950408889634f
#define LN2     0.6931471805599453f
#define BIGQ (BIGF * INV_LN2)

// Diag-major distances, PRE-SCALED by 1/ln2: g_Dd[b][k][i] = D[i][k-i]/ln2
__device__ float g_Dd[(size_t)B_ * KD * N_];   // ~67 MB static scratch

__device__ __forceinline__ float ex2f(float x) {
    float y; asm("ex2.approx.ftz.f32 %0, %1;" : "=f"(y) : "f"(x)); return y;
}
__device__ __forceinline__ float lg2f(float x) {
    float y; asm("lg2.approx.ftz.f32 %0, %1;" : "=f"(y) : "f"(x)); return y;
}

// ---------------------------------------------------------------------------
// Kernel 1: distance tiles, written DIAG-MAJOR, scaled by 1/ln2.
// 64x64 tile, 256 threads, 4x4 micro-tile; norms computed in-block.
// ---------------------------------------------------------------------------
#define TS  64
#define SP  68
#define TSP 66

__global__ __launch_bounds__(256) void dist_kernel(const float* __restrict__ x,
                                                   const float* __restrict__ y) {
    __shared__ float Xs[D_ * SP];
    __shared__ float Ys[D_ * SP];
    __shared__ float xn[TS], yn[TS];

    const int b  = blockIdx.z;
    const int i0 = blockIdx.y * TS;
    const int j0 = blockIdx.x * TS;
    const float* xb = x + ((size_t)b * N_ + i0) * D_;
    const float* yb = y + ((size_t)b * M_ + j0) * D_;
    const int tid = threadIdx.x;

#pragma unroll
    for (int it = 0; it < 4; ++it) {
        int f   = tid + it * 256;
        int row = f & 63;
        int c4  = f >> 6;
        float4 vx = *(const float4*)(xb + row * D_ + c4 * 4);
        float4 vy = *(const float4*)(yb + row * D_ + c4 * 4);
        Xs[(c4 * 4 + 0) * SP + row] = vx.x;
        Xs[(c4 * 4 + 1) * SP + row] = vx.y;
        Xs[(c4 * 4 + 2) * SP + row] = vx.z;
        Xs[(c4 * 4 + 3) * SP + row] = vx.w;
        Ys[(c4 * 4 + 0) * SP + row] = vy.x;
        Ys[(c4 * 4 + 1) * SP + row] = vy.y;
        Ys[(c4 * 4 + 2) * SP + row] = vy.z;
        Ys[(c4 * 4 + 3) * SP + row] = vy.w;
    }
    __syncthreads();

    if (tid < 64) {
        float s = 0.f;
#pragma unroll
        for (int k = 0; k < D_; ++k) { float v = Xs[k * SP + tid]; s = fmaf(v, v, s); }
        xn[tid] = s;
    } else if (tid < 128) {
        int r = tid - 64;
        float s = 0.f;
#pragma unroll
        for (int k = 0; k < D_; ++k) { float v = Ys[k * SP + r]; s = fmaf(v, v, s); }
        yn[r] = s;
    }
    __syncthreads();

    const int tx = tid & 15, ty = tid >> 4;
    const int ia = ty * 4, ja = tx * 4;

    float acc[4][4] = {};
#pragma unroll
    for (int k = 0; k < D_; ++k) {
        float4 a  = *(const float4*)&Xs[k * SP + ia];
        float4 bb = *(const float4*)&Ys[k * SP + ja];
        float av[4] = {a.x, a.y, a.z, a.w};
        float bv[4] = {bb.x, bb.y, bb.z, bb.w};
#pragma unroll
        for (int r = 0; r < 4; ++r)
#pragma unroll
            for (int c = 0; c < 4; ++c)
                acc[r][c] = fmaf(av[r], bv[c], acc[r][c]);
    }

    float x2v[4], y2v[4];
#pragma unroll
    for (int r = 0; r < 4; ++r) x2v[r] = xn[ia + r];
#pragma unroll
    for (int c = 0; c < 4; ++c) y2v[c] = yn[ja + c];

    __syncthreads();
    float* Ts = Xs;   // reuse (needs 64*66 <= 64*68)

#pragma unroll
    for (int r = 0; r < 4; ++r)
#pragma unroll
        for (int c = 0; c < 4; ++c)
            Ts[(ia + r) * TSP + (ja + c)] =
                fmaf(-2.f, acc[r][c], x2v[r] + y2v[c]) * INV_LN2;
    __syncthreads();

    float* Dd = g_Dd + (size_t)b * KD * N_;
    const int kbase = i0 + j0;
#pragma unroll
    for (int it = 0; it < 16; ++it) {
        int f  = it * 256 + tid;                  // 0..4095
        int fr = (f < 2080) ? f : 4095 - f;
        int kl = (int)(0.5f * (sqrtf((float)(8 * fr + 1)) - 1.0f));
        if ((kl + 1) * (kl + 2) / 2 <= fr) kl++;
        if (kl * (kl + 1) / 2 > fr)       kl--;
        int tt = fr - kl * (kl + 1) / 2;
        int i, kg;
        if (f < 2080) { kg = kl;       i = tt;      }
        else          { kg = 126 - kl; i = 63 - tt; }
        int j = kg - i;
        Dd[(size_t)(kbase + kg) * N_ + (i0 + i)] = Ts[i * TSP + j];
    }
}

// ---------------------------------------------------------------------------
// Kernel 2: soft-DTW, skewed row-pipeline with deferred-log softmin.
// 512 threads = 16 warps per batch. Lane l of warp w owns row 32w+l+1 and
// sweeps columns 1..512; lane i lags lane i-1 by 1 step (deps via shfl_up),
// warp w lags warp w-1 by 64 steps (boundary row via smem ring, barrier once
// per 32-step round). State (q,s) represents R = (q - log2 s)*ln2; per cell:
//   m = min(q0,q1,q2); s' = s0*2^(m-q0)+s1*2^(m-q1)+s2*2^(m-q2); q' = d+m.
// No log in the loop (renorm q -= log2 s once per round; exact rearrangement).
// ---------------------------------------------------------------------------
#define WARPS_  16
#define LAGW    64            // inter-warp lag in steps
#define RC      32            // steps per round (barrier period)
#define TMAXP   (M_ + 31)     // last local step a warp computes (543)
#define NROUNDS 47            // ceil((512 + 15*64 + 31) / 32)

__global__ __launch_bounds__(512) void dtw_kernel(float* __restrict__ out) {
    __shared__ float ringq[WARPS_][128];
    __shared__ float rings[WARPS_][128];

    const int b   = blockIdx.x;
    const int tid = threadIdx.x;
    const int w   = tid >> 5;
    const int l   = tid & 31;
    const float* Dq = g_Dd + (size_t)b * KD * N_;
    const int drow = 32 * w + l;            // element index within a diagonal

    float q2 = BIGQ, s2 = 1.f;              // own R[i][j-1]
    float hq = BIGQ, hs = 1.f;              // held r1 from prev step -> r0 now

    for (int r = 0; r < NROUNDS; ++r) {
        int Tb = r * RC + 1 - LAGW * w;     // local step T' of first step
        if (Tb + (RC - 1) >= 1 && Tb <= TMAXP) {
#pragma unroll
            for (int c = 0; c < RC; ++c) {
                int Tp = Tb + c;
                int j  = Tp - l;            // this lane's column

                float sq = __shfl_up_sync(0xffffffffu, q2, 1);
                float ss = __shfl_up_sync(0xffffffffu, s2, 1);
                if (l == 0) {
                    if (w > 0) {
                        int ri = Tp & 127;
                        sq = ringq[w - 1][ri];
                        ss = rings[w - 1][ri];
                    } else { sq = BIGQ; ss = 1.f; }
                }
                float q1 = sq, s1 = ss;     // R[i-1][j]
                float q0 = hq, s0 = hs;     // R[i-1][j-1]
                float qc = q2, sc = s2;     // R[i][j-1]
                if (j == 1) { q0 = BIGQ; s0 = 1.f; qc = BIGQ; sc = 1.f; }
                if (w == 0 && l == 0) {
                    q1 = BIGQ; s1 = 1.f;
                    q0 = (j == 1) ? 0.f : BIGQ; s0 = 1.f;
                }

                int kD = 32 * w + Tp - 1;                 // (i-1)+(j-1)
                int kc = min(max(kD, 0), KD - 1);
                float dq = __ldg(&Dq[(size_t)kc * N_ + drow]);

                float m  = fminf(fminf(q0, q1), qc);
                float e0 = ex2f(m - q0);
                float e1 = ex2f(m - q1);
                float e2 = ex2f(m - qc);
                float sn = fmaf(s0, e0, fmaf(s1, e1, sc * e2));
                float qn = dq + m;

                bool act = (j >= 1) && (j <= M_);
                if (act) { q2 = qn; s2 = sn; }
                hq = sq; hs = ss;

                if (l == 31 && act && w < WARPS_ - 1) {
                    ringq[w][j & 127] = q2;
                    rings[w][j & 127] = s2;
                }
            }
            // value-preserving renorm keeps s in fp32 range (s >= 1 in-round)
            q2 -= lg2f(s2);
            s2 = 1.f;
        }
        __syncthreads();
    }

    if (w == WARPS_ - 1 && l == 31)
        out[b] = (q2 - lg2f(s2)) * LN2;     // R[512][512]
}

// ---------------------------------------------------------------------------
extern "C" void kernel_launch(void* const* d_in, const int* in_sizes, int n_in,
                              void* d_out, int out_size) {
    const float* x = (const float*)d_in[0];
    const float* y = (const float*)d_in[1];
    float* out = (float*)d_out;

    dim3 dgrid(M_ / TS, N_ / TS, B_);
    dist_kernel<<<dgrid, 256>>>(x, y);
    dtw_kernel<<<B_, 512>>>(out);
}

// round 8
// speedup vs baseline: 2.0727x; 1.5666x over previous
#include <cuda_runtime.h>

#define B_   32
#define N_   512
#define M_   512
#define D_   64
#define KD   (N_ + M_ - 1)          // 1023 anti-diagonals of the D matrix
#define BIGF 1e10f
#define INV_LN2 1.4426950408889634f
#define LN2     0.6931471805599453f
#define BIGQ (BIGF * INV_LN2)

// Tiled diag-major distances, pre-scaled by 1/ln2:
//   g_Dt[((b*32 + kD/32)*16 + row/32)*1024 + (kD%32)*32 + (row%32)]
// where row = i-1 (0..511), kD = (i-1)+(j-1) (0..1022; slot 1023 padding).
__device__ float g_Dt[(size_t)B_ * 32 * 16 * 1024];   // 64 MB static scratch

__device__ __forceinline__ float ex2f(float x) {
    float y; asm("ex2.approx.ftz.f32 %0, %1;" : "=f"(y) : "f"(x)); return y;
}
__device__ __forceinline__ float lg2f(float x) {
    float y; asm("lg2.approx.ftz.f32 %0, %1;" : "=f"(y) : "f"(x)); return y;
}

// ---------------------------------------------------------------------------
// Kernel 1: distance tiles, drained into the TILED diag-major layout.
// 64x64 tile, 256 threads, 4x4 micro-tile; norms computed in-block.
// ---------------------------------------------------------------------------
#define TS  64
#define SP  68
#define TSP 66

__global__ __launch_bounds__(256) void dist_kernel(const float* __restrict__ x,
                                                   const float* __restrict__ y) {
    __shared__ float Xs[D_ * SP];
    __shared__ float Ys[D_ * SP];
    __shared__ float xn[TS], yn[TS];

    const int b  = blockIdx.z;
    const int i0 = blockIdx.y * TS;
    const int j0 = blockIdx.x * TS;
    const float* xb = x + ((size_t)b * N_ + i0) * D_;
    const float* yb = y + ((size_t)b * M_ + j0) * D_;
    const int tid = threadIdx.x;

#pragma unroll
    for (int it = 0; it < 4; ++it) {
        int f   = tid + it * 256;
        int row = f & 63;
        int c4  = f >> 6;
        float4 vx = *(const float4*)(xb + row * D_ + c4 * 4);
        float4 vy = *(const float4*)(yb + row * D_ + c4 * 4);
        Xs[(c4 * 4 + 0) * SP + row] = vx.x;
        Xs[(c4 * 4 + 1) * SP + row] = vx.y;
        Xs[(c4 * 4 + 2) * SP + row] = vx.z;
        Xs[(c4 * 4 + 3) * SP + row] = vx.w;
        Ys[(c4 * 4 + 0) * SP + row] = vy.x;
        Ys[(c4 * 4 + 1) * SP + row] = vy.y;
        Ys[(c4 * 4 + 2) * SP + row] = vy.z;
        Ys[(c4 * 4 + 3) * SP + row] = vy.w;
    }
    __syncthreads();

    if (tid < 64) {
        float s = 0.f;
#pragma unroll
        for (int k = 0; k < D_; ++k) { float v = Xs[k * SP + tid]; s = fmaf(v, v, s); }
        xn[tid] = s;
    } else if (tid < 128) {
        int r = tid - 64;
        float s = 0.f;
#pragma unroll
        for (int k = 0; k < D_; ++k) { float v = Ys[k * SP + r]; s = fmaf(v, v, s); }
        yn[r] = s;
    }
    __syncthreads();

    const int tx = tid & 15, ty = tid >> 4;
    const int ia = ty * 4, ja = tx * 4;

    float acc[4][4] = {};
#pragma unroll
    for (int k = 0; k < D_; ++k) {
        float4 a  = *(const float4*)&Xs[k * SP + ia];
        float4 bb = *(const float4*)&Ys[k * SP + ja];
        float av[4] = {a.x, a.y, a.z, a.w};
        float bv[4] = {bb.x, bb.y, bb.z, bb.w};
#pragma unroll
        for (int r = 0; r < 4; ++r)
#pragma unroll
            for (int c = 0; c < 4; ++c)
                acc[r][c] = fmaf(av[r], bv[c], acc[r][c]);
    }

    float x2v[4], y2v[4];
#pragma unroll
    for (int r = 0; r < 4; ++r) x2v[r] = xn[ia + r];
#pragma unroll
    for (int c = 0; c < 4; ++c) y2v[c] = yn[ja + c];

    __syncthreads();
    float* Ts = Xs;   // reuse (needs 64*66 <= 64*68)

#pragma unroll
    for (int r = 0; r < 4; ++r)
#pragma unroll
        for (int c = 0; c < 4; ++c)
            Ts[(ia + r) * TSP + (ja + c)] =
                fmaf(-2.f, acc[r][c], x2v[r] + y2v[c]) * INV_LN2;
    __syncthreads();

    float* Dd = g_Dt + (size_t)b * (32 * 16 * 1024);
    const int kbase = i0 + j0;
#pragma unroll
    for (int it = 0; it < 16; ++it) {
        int f  = it * 256 + tid;                  // 0..4095
        int fr = (f < 2080) ? f : 4095 - f;
        int kl = (int)(0.5f * (sqrtf((float)(8 * fr + 1)) - 1.0f));
        if ((kl + 1) * (kl + 2) / 2 <= fr) kl++;
        if (kl * (kl + 1) / 2 > fr)       kl--;
        int tt = fr - kl * (kl + 1) / 2;
        int i, kg;
        if (f < 2080) { kg = kl;       i = tt;      }
        else          { kg = 126 - kl; i = 63 - tt; }
        int j   = kg - i;
        int kD  = kbase + kg;
        int row = i0 + i;
        Dd[((((kD >> 5) << 4) + (row >> 5)) << 10) + ((kD & 31) << 5) + (row & 31)]
            = Ts[i * TSP + j];
    }
}

// ---------------------------------------------------------------------------
// Kernel 2: soft-DTW, skewed row-pipeline, deferred-log softmin,
// register-double-buffered tiled D feed (one full round of prefetch slack).
// Warp w round r consumes tile (kt=r-w, wt=w): dq(step c, lane l) = tile[c*32+l].
// ---------------------------------------------------------------------------
#define WARPS_  16
#define RC      32            // steps per round (barrier period)
#define NROUNDS 47            // last active round = 2*15+16 = 46

__global__ void __launch_bounds__(512, 1) dtw_kernel(float* __restrict__ out) {
    __shared__ float ringq[WARPS_][128];
    __shared__ float rings[WARPS_][128];

    const int b   = blockIdx.x;
    const int tid = threadIdx.x;
    const int w   = tid >> 5;
    const int l   = tid & 31;
    const float* Dbase = g_Dt + (size_t)b * (32 * 16 * 1024);

    float q2 = BIGQ, s2 = 1.f;              // own R[i][j-1]
    float hq = BIGQ, hs = 1.f;              // held r1 from prev step -> r0 now
    float dcur[RC], dnxt[RC];

    // Preload warp 0's first tile (kt=0, wt=0); other warps get theirs via
    // the round-(2w-1) prefetch below.
    if (w == 0) {
        const float* tp = Dbase + l;
#pragma unroll
        for (int c = 0; c < RC; ++c) dcur[c] = __ldg(tp + c * 32);
    }

    for (int r = 0; r < NROUNDS; ++r) {
        const bool act_now = (r >= 2 * w) && (r <= 2 * w + 16);
        const bool act_nxt = (r + 1 >= 2 * w) && (r + 1 <= 2 * w + 16);

        // Prefetch next round's tile: 32 independent coalesced LDGs (MLP=32),
        // consumed only after the next barrier -> full-round latency slack.
        if (act_nxt) {
            const float* tp = Dbase + (((size_t)(r + 1 - w) * 16 + w) << 10) + l;
#pragma unroll
            for (int c = 0; c < RC; ++c) dnxt[c] = __ldg(tp + c * 32);
        }

        if (act_now) {
            const int Tb0 = 32 * r + 1 - 64 * w;   // local step of c=0
#pragma unroll
            for (int c = 0; c < RC; ++c) {
                int Tp = Tb0 + c;
                int j  = Tp - l;                   // this lane's column

                float sq = __shfl_up_sync(0xffffffffu, q2, 1);
                float ss = __shfl_up_sync(0xffffffffu, s2, 1);
                if (l == 0) {
                    if (w > 0) {
                        int ri = Tp & 127;
                        sq = ringq[w - 1][ri];
                        ss = rings[w - 1][ri];
                    } else { sq = BIGQ; ss = 1.f; }
                }
                float q1 = sq, s1 = ss;            // R[i-1][j]
                float q0 = hq, s0 = hs;            // R[i-1][j-1]
                float qc = q2, sc = s2;            // R[i][j-1]
                if (j == 1) { q0 = BIGQ; s0 = 1.f; qc = BIGQ; sc = 1.f; }
                if (w == 0 && l == 0) {
                    q1 = BIGQ; s1 = 1.f;
                    q0 = (j == 1) ? 0.f : BIGQ; s0 = 1.f;
                }

                float dq = dcur[c];
                // early min of the two locally-available terms; shfl result last
                float m  = fminf(fminf(q0, qc), q1);
                float e0 = ex2f(m - q0);
                float e1 = ex2f(m - q1);
                float e2 = ex2f(m - qc);
                float sn = fmaf(s0, e0, fmaf(s1, e1, sc * e2));
                float qn = dq + m;

                bool act = (j >= 1) && (j <= M_);
                if (act) { q2 = qn; s2 = sn; }
                hq = sq; hs = ss;

                if (l == 31 && act && w < WARPS_ - 1) {
                    ringq[w][j & 127] = q2;
                    rings[w][j & 127] = s2;
                }
            }
            // value-preserving renorm keeps s in fp32 range (s >= 1 in-round)
            q2 -= lg2f(s2);
            s2 = 1.f;
        }

#pragma unroll
        for (int c = 0; c < RC; ++c) dcur[c] = dnxt[c];
        __syncthreads();
    }

    if (w == WARPS_ - 1 && l == 31)
        out[b] = (q2 - lg2f(s2)) * LN2;     // R[512][512]
}

// ---------------------------------------------------------------------------
extern "C" void kernel_launch(void* const* d_in, const int* in_sizes, int n_in,
                              void* d_out, int out_size) {
    const float* x = (const float*)d_in[0];
    const float* y = (const float*)d_in[1];
    float* out = (float*)d_out;

    dim3 dgrid(M_ / TS, N_ / TS, B_);
    dist_kernel<<<dgrid, 256>>>(x, y);
    dtw_kernel<<<B_, 512>>>(out);
}

// round 9
// speedup vs baseline: 2.3911x; 1.1536x over previous
#include <cuda_runtime.h>

#define B_   32
#define N_   512
#define M_   512
#define D_   64
#define KD   (N_ + M_ - 1)          // 1023 anti-diagonals of the D matrix
#define BIGF 1e10f
#define INV_LN2 1.4426950408889634f
#define LN2     0.6931471805599453f
#define BIGQ (BIGF * INV_LN2)

// Tiled diag-major distances, pre-scaled by 1/ln2:
//   g_Dt[((b*32 + kD/32)*16 + row/32)*1024 + (kD%32)*32 + (row%32)]
// where row = i-1 (0..511), kD = (i-1)+(j-1) (0..1022; slot 1023 padding).
__device__ float g_Dt[(size_t)B_ * 32 * 16 * 1024];   // 64 MB static scratch

__device__ __forceinline__ float ex2f(float x) {
    float y; asm("ex2.approx.ftz.f32 %0, %1;" : "=f"(y) : "f"(x)); return y;
}
__device__ __forceinline__ float lg2f(float x) {
    float y; asm("lg2.approx.ftz.f32 %0, %1;" : "=f"(y) : "f"(x)); return y;
}

// ---------------------------------------------------------------------------
// Kernel 1: distance tiles, drained into the TILED diag-major layout.
// (unchanged from R8)
// ---------------------------------------------------------------------------
#define TS  64
#define SP  68
#define TSP 66

__global__ __launch_bounds__(256) void dist_kernel(const float* __restrict__ x,
                                                   const float* __restrict__ y) {
    __shared__ float Xs[D_ * SP];
    __shared__ float Ys[D_ * SP];
    __shared__ float xn[TS], yn[TS];

    const int b  = blockIdx.z;
    const int i0 = blockIdx.y * TS;
    const int j0 = blockIdx.x * TS;
    const float* xb = x + ((size_t)b * N_ + i0) * D_;
    const float* yb = y + ((size_t)b * M_ + j0) * D_;
    const int tid = threadIdx.x;

#pragma unroll
    for (int it = 0; it < 4; ++it) {
        int f   = tid + it * 256;
        int row = f & 63;
        int c4  = f >> 6;
        float4 vx = *(const float4*)(xb + row * D_ + c4 * 4);
        float4 vy = *(const float4*)(yb + row * D_ + c4 * 4);
        Xs[(c4 * 4 + 0) * SP + row] = vx.x;
        Xs[(c4 * 4 + 1) * SP + row] = vx.y;
        Xs[(c4 * 4 + 2) * SP + row] = vx.z;
        Xs[(c4 * 4 + 3) * SP + row] = vx.w;
        Ys[(c4 * 4 + 0) * SP + row] = vy.x;
        Ys[(c4 * 4 + 1) * SP + row] = vy.y;
        Ys[(c4 * 4 + 2) * SP + row] = vy.z;
        Ys[(c4 * 4 + 3) * SP + row] = vy.w;
    }
    __syncthreads();

    if (tid < 64) {
        float s = 0.f;
#pragma unroll
        for (int k = 0; k < D_; ++k) { float v = Xs[k * SP + tid]; s = fmaf(v, v, s); }
        xn[tid] = s;
    } else if (tid < 128) {
        int r = tid - 64;
        float s = 0.f;
#pragma unroll
        for (int k = 0; k < D_; ++k) { float v = Ys[k * SP + r]; s = fmaf(v, v, s); }
        yn[r] = s;
    }
    __syncthreads();

    const int tx = tid & 15, ty = tid >> 4;
    const int ia = ty * 4, ja = tx * 4;

    float acc[4][4] = {};
#pragma unroll
    for (int k = 0; k < D_; ++k) {
        float4 a  = *(const float4*)&Xs[k * SP + ia];
        float4 bb = *(const float4*)&Ys[k * SP + ja];
        float av[4] = {a.x, a.y, a.z, a.w};
        float bv[4] = {bb.x, bb.y, bb.z, bb.w};
#pragma unroll
        for (int r = 0; r < 4; ++r)
#pragma unroll
            for (int c = 0; c < 4; ++c)
                acc[r][c] = fmaf(av[r], bv[c], acc[r][c]);
    }

    float x2v[4], y2v[4];
#pragma unroll
    for (int r = 0; r < 4; ++r) x2v[r] = xn[ia + r];
#pragma unroll
    for (int c = 0; c < 4; ++c) y2v[c] = yn[ja + c];

    __syncthreads();
    float* Ts = Xs;   // reuse (needs 64*66 <= 64*68)

#pragma unroll
    for (int r = 0; r < 4; ++r)
#pragma unroll
        for (int c = 0; c < 4; ++c)
            Ts[(ia + r) * TSP + (ja + c)] =
                fmaf(-2.f, acc[r][c], x2v[r] + y2v[c]) * INV_LN2;
    __syncthreads();

    float* Dd = g_Dt + (size_t)b * (32 * 16 * 1024);
    const int kbase = i0 + j0;
#pragma unroll
    for (int it = 0; it < 16; ++it) {
        int f  = it * 256 + tid;                  // 0..4095
        int fr = (f < 2080) ? f : 4095 - f;
        int kl = (int)(0.5f * (sqrtf((float)(8 * fr + 1)) - 1.0f));
        if ((kl + 1) * (kl + 2) / 2 <= fr) kl++;
        if (kl * (kl + 1) / 2 > fr)       kl--;
        int tt = fr - kl * (kl + 1) / 2;
        int i, kg;
        if (f < 2080) { kg = kl;       i = tt;      }
        else          { kg = 126 - kl; i = 63 - tt; }
        int j   = kg - i;
        int kD  = kbase + kg;
        int row = i0 + i;
        Dd[((((kD >> 5) << 4) + (row >> 5)) << 10) + ((kD & 31) << 5) + (row & 31)]
            = Ts[i * TSP + j];
    }
}

// ---------------------------------------------------------------------------
// Kernel 2: soft-DTW, skewed row-pipeline, deferred-log softmin, tiled D feed.
// This round: branch-free inner step + mode-peeled rounds.
//   MODE 0 (rho==0):    head  — j<1 inactivity, j==1 column-0 seeds, R[0][0]
//   MODE 1 (1..15):     clean — no boundary logic at all
//   MODE 2 (rho==16):   tail  — j>512 deactivation only
// Ring is float2 (q,s); all lanes issue one broadcast LDS.64 per step and SEL
// it into lane 0 (row 16 of the ring is a constant BIGQ row used when w==0).
// Boundary publish is a single predicated STS.64 from lane 31.
// ---------------------------------------------------------------------------
#define WARPS_  16
#define RC      32            // steps per round (barrier period)
#define NROUNDS 47            // last active round = 2*15+16 = 46

template <int MODE>
__device__ __forceinline__ void round_body(
    int Tb0, int l, bool p0, bool p31, bool w0l0,
    const float2* __restrict__ ringrd, float2* __restrict__ ringwr,
    const float* __restrict__ dcur,
    float& q2, float& s2, float& hq, float& hs)
{
#pragma unroll
    for (int c = 0; c < RC; ++c) {
        const int Tp = Tb0 + c;

        float sq = __shfl_up_sync(0xffffffffu, q2, 1);
        float ss = __shfl_up_sync(0xffffffffu, s2, 1);
        float2 rv = ringrd[Tp & 127];          // broadcast LDS.64
        if (p0) { sq = rv.x; ss = rv.y; }      // SELs

        float q1 = sq, s1 = ss;                // R[i-1][j]
        float q0 = hq, s0 = hs;                // R[i-1][j-1]
        float qc = q2, sc = s2;                // R[i][j-1]

        if (MODE == 0) {
            const int j = Tp - l;
            if (j == 1) { q0 = BIGQ; s0 = 1.f; qc = BIGQ; sc = 1.f; }
            if (w0l0) {
                q1 = BIGQ; s1 = 1.f;
                q0 = (j == 1) ? 0.f : BIGQ; s0 = 1.f;
            }
        }

        float m  = fminf(fminf(q0, qc), q1);
        float e0 = ex2f(m - q0);
        float e1 = ex2f(m - q1);
        float e2 = ex2f(m - qc);
        float sn = fmaf(s0, e0, fmaf(s1, e1, sc * e2));
        float qn = dcur[c] + m;

        bool act = true;
        if (MODE == 0) act = (Tp - l) >= 1;
        if (MODE == 2) act = (Tp - l) <= M_;
        if (act) { q2 = qn; s2 = sn; }         // SELs
        hq = sq; hs = ss;

        bool wr = p31;
        if (MODE == 0 || MODE == 2) wr = p31 && act;
        if (wr) ringwr[(Tp - 31) & 127] = make_float2(q2, s2);  // @p STS.64
    }
    // value-preserving renorm keeps s in fp32 range (s >= 1 in-round)
    q2 -= lg2f(s2);
    s2 = 1.f;
}

__global__ void __launch_bounds__(512, 1) dtw_kernel(float* __restrict__ out) {
    __shared__ float2 ring[WARPS_ + 1][128];   // row 16 = constant BIGQ row

    const int b   = blockIdx.x;
    const int tid = threadIdx.x;
    const int w   = tid >> 5;
    const int l   = tid & 31;
    const float* Dbase = g_Dt + (size_t)b * (32 * 16 * 1024);

    // constant source row for warp 0's "previous boundary"
    if (tid < 128) ring[WARPS_][tid] = make_float2(BIGQ, 1.f);

    const bool  p0   = (l == 0);
    const bool  p31  = (l == 31);
    const bool  w0l0 = (w == 0) && (l == 0);
    const float2* ringrd = (w == 0) ? ring[WARPS_] : ring[w - 1];
    float2*       ringwr = ring[w];

    float q2 = BIGQ, s2 = 1.f;              // own R[i][j-1]
    float hq = BIGQ, hs = 1.f;              // held r1 from prev step -> r0 now
    float dcur[RC], dnxt[RC];

    // Preload warp 0's first tile (kt=0, wt=0).
    if (w == 0) {
        const float* tp = Dbase + l;
#pragma unroll
        for (int c = 0; c < RC; ++c) dcur[c] = __ldg(tp + c * 32);
    }
    __syncthreads();                        // ring row 16 visible

    for (int r = 0; r < NROUNDS; ++r) {
        const int  rho     = r - 2 * w;
        const bool act_nxt = (r + 1 >= 2 * w) && (r + 1 <= 2 * w + 16);

        // Prefetch next round's tile: 32 independent coalesced LDGs.
        if (act_nxt) {
            const float* tp = Dbase + (((size_t)(r + 1 - w) * 16 + w) << 10) + l;
#pragma unroll
            for (int c = 0; c < RC; ++c) dnxt[c] = __ldg(tp + c * 32);
        }

        const int Tb0 = 32 * r + 1 - 64 * w;
        if (rho == 0)
            round_body<0>(Tb0, l, p0, p31, w0l0, ringrd, ringwr, dcur, q2, s2, hq, hs);
        else if (rho >= 1 && rho <= 15)
            round_body<1>(Tb0, l, p0, p31, w0l0, ringrd, ringwr, dcur, q2, s2, hq, hs);
        else if (rho == 16)
            round_body<2>(Tb0, l, p0, p31, w0l0, ringrd, ringwr, dcur, q2, s2, hq, hs);

        if (act_nxt) {
#pragma unroll
            for (int c = 0; c < RC; ++c) dcur[c] = dnxt[c];
        }
        __syncthreads();
    }

    if (w == WARPS_ - 1 && l == 31)
        out[b] = (q2 - lg2f(s2)) * LN2;     // R[512][512]
}

// ---------------------------------------------------------------------------
extern "C" void kernel_launch(void* const* d_in, const int* in_sizes, int n_in,
                              void* d_out, int out_size) {
    const float* x = (const float*)d_in[0];
    const float* y = (const float*)d_in[1];
    float* out = (float*)d_out;

    dim3 dgrid(M_ / TS, N_ / TS, B_);
    dist_kernel<<<dgrid, 256>>>(x, y);
    dtw_kernel<<<B_, 512>>>(out);
}